// round 2
// baseline (speedup 1.0000x reference)
#include <cuda_runtime.h>
#include <math.h>

#define EPSF 1e-8f
#define NB     64
#define NTOKP1 785
#define DIM    768
#define FH     28
#define NTOK   784
#define IMG    448
#define NCH    3
#define TOPK   8
#define PE     16
#define TGRP   7          // token groups per batch
#define TPG    112        // tokens per group (784/7)

// scratch: per-batch distances and crop box (no allocations allowed)
__device__ float g_dist[NB][NTOK];
__device__ int   g_box[NB][4];

// ---------------------------------------------------------------------------
// Kernel A1: cosine distances. grid = (7 token-groups, 64 batches), 256 thr.
// Warp-per-token, float4-coalesced. 448 CTAs -> full chip.
// ---------------------------------------------------------------------------
__global__ __launch_bounds__(256)
void sim_kernel(const float* __restrict__ x) {
    const int grp = blockIdx.x;
    const int b   = blockIdx.y;
    const float* __restrict__ xb = x + (size_t)b * NTOKP1 * DIM;

    __shared__ float gs[DIM];
    __shared__ float red[8];

    const int tid  = threadIdx.x;
    const int lane = tid & 31;
    const int wid  = tid >> 5;

    // Load global token g into smem + sum of squares
    float ss = 0.f;
    for (int j = tid; j < DIM; j += 256) {
        float v = __ldg(xb + j);
        gs[j] = v;
        ss += v * v;
    }
    #pragma unroll
    for (int o = 16; o; o >>= 1) ss += __shfl_xor_sync(0xffffffffu, ss, o);
    if (lane == 0) red[wid] = ss;
    __syncthreads();
    if (tid == 0) {
        float s = 0.f;
        #pragma unroll
        for (int w = 0; w < 8; w++) s += red[w];
        red[0] = s;
    }
    __syncthreads();
    const float gn = fmaxf(sqrtf(red[0]), EPSF);

    // 8 warps cover 112 tokens: 14 tokens/warp, strided for coalescing
    const int t_base = grp * TPG;
    for (int t = t_base + wid; t < t_base + TPG; t += 8) {
        const float* __restrict__ lr = xb + (size_t)(t + 1) * DIM;
        float dot = 0.f, ls = 0.f;
        #pragma unroll
        for (int i = 0; i < 6; i++) {
            const int j = i * 128 + lane * 4;
            const float4 lv = *(const float4*)(lr + j);
            const float4 gv = *(const float4*)(gs + j);
            dot += lv.x * gv.x + lv.y * gv.y + lv.z * gv.z + lv.w * gv.w;
            ls  += lv.x * lv.x + lv.y * lv.y + lv.z * lv.z + lv.w * lv.w;
        }
        #pragma unroll
        for (int o = 16; o; o >>= 1) {
            dot += __shfl_xor_sync(0xffffffffu, dot, o);
            ls  += __shfl_xor_sync(0xffffffffu, ls, o);
        }
        if (lane == 0) {
            const float ln = fmaxf(sqrtf(ls), EPSF);
            g_dist[b][t] = dot / (gn * ln);
        }
    }
}

// ---------------------------------------------------------------------------
// Kernel A2: top-8 (ties -> lowest index, matching lax.top_k) -> crop box.
// One warp per batch.
// ---------------------------------------------------------------------------
__global__ __launch_bounds__(32)
void topk_box_kernel() {
    const int b    = blockIdx.x;
    const int lane = threadIdx.x;

    __shared__ float dist[NTOK];
    for (int t = lane; t < NTOK; t += 32) dist[t] = g_dist[b][t];
    __syncwarp();

    int minR = FH, maxR = -1, minC = FH, maxC = -1;
    for (int k = 0; k < TOPK; k++) {
        float bv = -3e38f;
        int   bi = 0x7fffffff;
        for (int t = lane; t < NTOK; t += 32) {
            const float v = dist[t];
            if (v > bv || (v == bv && t < bi)) { bv = v; bi = t; }
        }
        #pragma unroll
        for (int o = 16; o; o >>= 1) {
            const float ov = __shfl_xor_sync(0xffffffffu, bv, o);
            const int   oi = __shfl_xor_sync(0xffffffffu, bi, o);
            if (ov > bv || (ov == bv && oi < bi)) { bv = ov; bi = oi; }
        }
        if (lane == 0) dist[bi] = -3e38f;
        __syncwarp();
        const int r = bi / FH, c = bi % FH;
        minR = min(minR, r); maxR = max(maxR, r);
        minC = min(minC, c); maxC = max(maxC, c);
    }
    if (lane == 0) {
        const int x_i = minR * PE, x_f = maxR * PE;
        const int y_i = minC * PE, y_f = maxC * PE;
        const int x0 = max(x_i, 0);
        const int y0 = max(y_i, 0);
        const int x1 = min(max(x_f, x_i + PE), IMG);
        const int y1 = min(max(y_f, y_i + PE), IMG);
        g_box[b][0] = x0; g_box[b][1] = x1;
        g_box[b][2] = y0; g_box[b][3] = y1;
    }
}

// ---------------------------------------------------------------------------
// Kernel B: bilinear crop-resize (align_corners). One thread per output pixel.
// grid = (448 rows, 3 channels, 64 batches), block = 448 threads.
// ---------------------------------------------------------------------------
__global__ __launch_bounds__(IMG)
void crop_resize_kernel(const float* __restrict__ images, float* __restrict__ out) {
    const int oy = blockIdx.x;
    const int c  = blockIdx.y;
    const int b  = blockIdx.z;
    const int ox = threadIdx.x;

    const int x0 = g_box[b][0], x1 = g_box[b][1];
    const int y0 = g_box[b][2], y1 = g_box[b][3];

    const float scale = (float)(1.0 / 447.0);
    const float hm1 = __fadd_rn((float)(x1 - x0), -1.0f);
    const float wm1 = __fadd_rn((float)(y1 - y0), -1.0f);

    // sy = x0 + oy*(h-1)*scale  (reference fp32 expression order, no FMA
    // contraction -> same rounding as XLA's mul/mul/add)
    const float sy = __fadd_rn((float)x0, __fmul_rn(__fmul_rn((float)oy, hm1), scale));
    const float sx = __fadd_rn((float)y0, __fmul_rn(__fmul_rn((float)ox, wm1), scale));

    const int ylo = (int)floorf(sy);
    const int xlo = (int)floorf(sx);
    const int yhi = min(ylo + 1, x1 - 1);
    const int xhi = min(xlo + 1, y1 - 1);
    const float wy = __fadd_rn(sy, -(float)ylo);
    const float wx = __fadd_rn(sx, -(float)xlo);

    const float* __restrict__ img = images + (size_t)(b * NCH + c) * IMG * IMG;
    const float v00 = __ldg(img + ylo * IMG + xlo);
    const float v01 = __ldg(img + ylo * IMG + xhi);
    const float v10 = __ldg(img + yhi * IMG + xlo);
    const float v11 = __ldg(img + yhi * IMG + xhi);

    const float r = (1.f - wy) * (1.f - wx) * v00
                  + (1.f - wy) * wx         * v01
                  + wy         * (1.f - wx) * v10
                  + wy         * wx         * v11;

    out[((size_t)(b * NCH + c) * IMG + oy) * IMG + ox] = r;
}

// ---------------------------------------------------------------------------
extern "C" void kernel_launch(void* const* d_in, const int* in_sizes, int n_in,
                              void* d_out, int out_size) {
    const float* x      = (const float*)d_in[0];   // (64, 785, 768) fp32
    const float* images = (const float*)d_in[1];   // (64, 3, 448, 448) fp32
    float* out = (float*)d_out;                    // (64, 3, 448, 448) fp32

    dim3 gridA(TGRP, NB);
    sim_kernel<<<gridA, 256>>>(x);
    topk_box_kernel<<<NB, 32>>>();
    dim3 gridB(IMG, NCH, NB);
    crop_resize_kernel<<<gridB, IMG>>>(images, out);
}

// round 3
// speedup vs baseline: 1.4878x; 1.4878x over previous
#include <cuda_runtime.h>
#include <math.h>

#define EPSF 1e-8f
#define NB     64
#define NTOKP1 785
#define DIM    768
#define FH     28
#define NTOK   784
#define IMG    448
#define NCH    3
#define TOPK   8
#define PE     16
#define TGRP   14         // token groups per batch
#define TPG    56         // tokens per group (784/14)
#define ROWT   16         // output rows per crop CTA

// scratch: per-batch distances and crop box (no allocations allowed)
__device__ float g_dist[NB][NTOK];
__device__ int   g_box[NB][4];

// ---------------------------------------------------------------------------
// Kernel A1: cosine distances. grid = (14 token-groups, 64 batches), 256 thr.
// Warp-per-token, float4-coalesced. 896 CTAs -> ~6 CTAs/SM.
// ---------------------------------------------------------------------------
__global__ __launch_bounds__(256)
void sim_kernel(const float* __restrict__ x) {
    const int grp = blockIdx.x;
    const int b   = blockIdx.y;
    const float* __restrict__ xb = x + (size_t)b * NTOKP1 * DIM;

    __shared__ float gs[DIM];
    __shared__ float red[8];

    const int tid  = threadIdx.x;
    const int lane = tid & 31;
    const int wid  = tid >> 5;

    // Load global token g into smem + sum of squares
    float ss = 0.f;
    for (int j = tid; j < DIM; j += 256) {
        float v = __ldg(xb + j);
        gs[j] = v;
        ss += v * v;
    }
    #pragma unroll
    for (int o = 16; o; o >>= 1) ss += __shfl_xor_sync(0xffffffffu, ss, o);
    if (lane == 0) red[wid] = ss;
    __syncthreads();
    if (tid == 0) {
        float s = 0.f;
        #pragma unroll
        for (int w = 0; w < 8; w++) s += red[w];
        red[0] = s;
    }
    __syncthreads();
    const float gn = fmaxf(sqrtf(red[0]), EPSF);

    // 8 warps cover 56 tokens: 7 tokens/warp, strided
    const int t_base = grp * TPG;
    for (int t = t_base + wid; t < t_base + TPG; t += 8) {
        const float* __restrict__ lr = xb + (size_t)(t + 1) * DIM;
        float dot = 0.f, ls = 0.f;
        #pragma unroll
        for (int i = 0; i < 6; i++) {
            const int j = i * 128 + lane * 4;
            const float4 lv = *(const float4*)(lr + j);
            const float4 gv = *(const float4*)(gs + j);
            dot += lv.x * gv.x + lv.y * gv.y + lv.z * gv.z + lv.w * gv.w;
            ls  += lv.x * lv.x + lv.y * lv.y + lv.z * lv.z + lv.w * lv.w;
        }
        #pragma unroll
        for (int o = 16; o; o >>= 1) {
            dot += __shfl_xor_sync(0xffffffffu, dot, o);
            ls  += __shfl_xor_sync(0xffffffffu, ls, o);
        }
        if (lane == 0) {
            const float ln = fmaxf(sqrtf(ls), EPSF);
            g_dist[b][t] = dot / (gn * ln);
        }
    }
}

// ---------------------------------------------------------------------------
// Kernel A2: top-8 (ties -> lowest index, matching lax.top_k) -> crop box.
// One warp per batch.
// ---------------------------------------------------------------------------
__global__ __launch_bounds__(32)
void topk_box_kernel() {
    const int b    = blockIdx.x;
    const int lane = threadIdx.x;

    __shared__ float dist[NTOK];
    for (int t = lane; t < NTOK; t += 32) dist[t] = g_dist[b][t];
    __syncwarp();

    int minR = FH, maxR = -1, minC = FH, maxC = -1;
    for (int k = 0; k < TOPK; k++) {
        float bv = -3e38f;
        int   bi = 0x7fffffff;
        for (int t = lane; t < NTOK; t += 32) {
            const float v = dist[t];
            if (v > bv || (v == bv && t < bi)) { bv = v; bi = t; }
        }
        #pragma unroll
        for (int o = 16; o; o >>= 1) {
            const float ov = __shfl_xor_sync(0xffffffffu, bv, o);
            const int   oi = __shfl_xor_sync(0xffffffffu, bi, o);
            if (ov > bv || (ov == bv && oi < bi)) { bv = ov; bi = oi; }
        }
        if (lane == 0) dist[bi] = -3e38f;
        __syncwarp();
        const int r = bi / FH, c = bi % FH;
        minR = min(minR, r); maxR = max(maxR, r);
        minC = min(minC, c); maxC = max(maxC, c);
    }
    if (lane == 0) {
        const int x_i = minR * PE, x_f = maxR * PE;
        const int y_i = minC * PE, y_f = maxC * PE;
        const int x0 = max(x_i, 0);
        const int y0 = max(y_i, 0);
        const int x1 = min(max(x_f, x_i + PE), IMG);
        const int y1 = min(max(y_f, y_i + PE), IMG);
        g_box[b][0] = x0; g_box[b][1] = x1;
        g_box[b][2] = y0; g_box[b][3] = y1;
    }
}

// ---------------------------------------------------------------------------
// Kernel B: bilinear crop-resize (align_corners), 16 output rows per CTA.
// grid = (28 row-tiles, 3 channels, 64 batches), block = 448 threads.
// Horizontal coords are row-invariant -> hoisted out of the row loop.
// ---------------------------------------------------------------------------
__global__ __launch_bounds__(IMG)
void crop_resize_kernel(const float* __restrict__ images, float* __restrict__ out) {
    const int rt = blockIdx.x;           // row tile
    const int c  = blockIdx.y;
    const int b  = blockIdx.z;
    const int ox = threadIdx.x;

    const int x0 = g_box[b][0], x1 = g_box[b][1];
    const int y0 = g_box[b][2], y1 = g_box[b][3];

    const float scale = (float)(1.0 / 447.0);
    const float hm1 = __fadd_rn((float)(x1 - x0), -1.0f);
    const float wm1 = __fadd_rn((float)(y1 - y0), -1.0f);

    // Horizontal (per-thread, constant across rows).
    // Reference fp32 expression order, no FMA contraction.
    const float sx = __fadd_rn((float)y0, __fmul_rn(__fmul_rn((float)ox, wm1), scale));
    const int   xlo = (int)floorf(sx);
    const int   xhi = min(xlo + 1, y1 - 1);
    const float wx  = __fadd_rn(sx, -(float)xlo);
    const float wx1 = 1.f - wx;

    const float* __restrict__ img = images + (size_t)(b * NCH + c) * IMG * IMG;
    float* __restrict__ op = out + ((size_t)(b * NCH + c) * IMG + rt * ROWT) * IMG + ox;

    #pragma unroll 4
    for (int r = 0; r < ROWT; r++) {
        const int oy = rt * ROWT + r;
        const float sy  = __fadd_rn((float)x0, __fmul_rn(__fmul_rn((float)oy, hm1), scale));
        const int   ylo = (int)floorf(sy);
        const int   yhi = min(ylo + 1, x1 - 1);
        const float wy  = __fadd_rn(sy, -(float)ylo);
        const float wy1 = 1.f - wy;

        const float* __restrict__ r0 = img + ylo * IMG;
        const float* __restrict__ r1 = img + yhi * IMG;
        const float v00 = __ldg(r0 + xlo);
        const float v01 = __ldg(r0 + xhi);
        const float v10 = __ldg(r1 + xlo);
        const float v11 = __ldg(r1 + xhi);

        const float res = wy1 * wx1 * v00 + wy1 * wx * v01
                        + wy  * wx1 * v10 + wy  * wx * v11;
        op[(size_t)r * IMG] = res;
    }
}

// ---------------------------------------------------------------------------
extern "C" void kernel_launch(void* const* d_in, const int* in_sizes, int n_in,
                              void* d_out, int out_size) {
    const float* x      = (const float*)d_in[0];   // (64, 785, 768) fp32
    const float* images = (const float*)d_in[1];   // (64, 3, 448, 448) fp32
    float* out = (float*)d_out;                    // (64, 3, 448, 448) fp32

    dim3 gridA(TGRP, NB);
    sim_kernel<<<gridA, 256>>>(x);
    topk_box_kernel<<<NB, 32>>>();
    dim3 gridB(IMG / ROWT, NCH, NB);
    crop_resize_kernel<<<gridB, IMG>>>(images, out);
}

// round 5
// speedup vs baseline: 1.5924x; 1.0704x over previous
#include <cuda_runtime.h>
#include <math.h>

#define EPSF 1e-8f
#define NB     64
#define NTOKP1 785
#define DIM    768
#define FH     28
#define NTOK   784
#define IMG    448
#define NCH    3
#define TOPK   8
#define PE     16
#define TGRP   28         // token groups per batch
#define TPG    28         // tokens per group (784/28)
#define ROWT   16         // output rows per crop CTA
#define SROWS  18         // staged input rows (>= max span + slack)

// scratch: per-batch distances and crop box (no allocations allowed)
__device__ float g_dist[NB][NTOK];
__device__ int   g_box[NB][4];

// ---------------------------------------------------------------------------
// Kernel A1: cosine distances. grid = (28 token-groups, 64 batches), 128 thr.
// Warp-per-token, float4-coalesced. 1792 small CTAs -> smooth waves.
// ---------------------------------------------------------------------------
__global__ __launch_bounds__(128)
void sim_kernel(const float* __restrict__ x) {
    const int grp = blockIdx.x;
    const int b   = blockIdx.y;
    const float* __restrict__ xb = x + (size_t)b * NTOKP1 * DIM;

    __shared__ float gs[DIM];
    __shared__ float red[4];

    const int tid  = threadIdx.x;
    const int lane = tid & 31;
    const int wid  = tid >> 5;

    // Load global token g into smem + sum of squares
    float ss = 0.f;
    for (int j = tid; j < DIM; j += 128) {
        float v = __ldg(xb + j);
        gs[j] = v;
        ss += v * v;
    }
    #pragma unroll
    for (int o = 16; o; o >>= 1) ss += __shfl_xor_sync(0xffffffffu, ss, o);
    if (lane == 0) red[wid] = ss;
    __syncthreads();
    if (tid == 0) red[0] = red[0] + red[1] + red[2] + red[3];
    __syncthreads();
    const float gn = fmaxf(sqrtf(red[0]), EPSF);

    // 4 warps cover 28 tokens: 7 tokens/warp, strided
    const int t_base = grp * TPG;
    for (int t = t_base + wid; t < t_base + TPG; t += 4) {
        const float* __restrict__ lr = xb + (size_t)(t + 1) * DIM;
        float dot = 0.f, ls = 0.f;
        #pragma unroll
        for (int i = 0; i < 6; i++) {
            const int j = i * 128 + lane * 4;
            const float4 lv = *(const float4*)(lr + j);
            const float4 gv = *(const float4*)(gs + j);
            dot += lv.x * gv.x + lv.y * gv.y + lv.z * gv.z + lv.w * gv.w;
            ls  += lv.x * lv.x + lv.y * lv.y + lv.z * lv.z + lv.w * lv.w;
        }
        #pragma unroll
        for (int o = 16; o; o >>= 1) {
            dot += __shfl_xor_sync(0xffffffffu, dot, o);
            ls  += __shfl_xor_sync(0xffffffffu, ls, o);
        }
        if (lane == 0) {
            const float ln = fmaxf(sqrtf(ls), EPSF);
            g_dist[b][t] = dot / (gn * ln);
        }
    }
}

// ---------------------------------------------------------------------------
// Kernel A2: top-8 (ties -> lowest index, matching lax.top_k) -> crop box.
// One warp per batch.
// ---------------------------------------------------------------------------
__global__ __launch_bounds__(32)
void topk_box_kernel() {
    const int b    = blockIdx.x;
    const int lane = threadIdx.x;

    __shared__ float dist[NTOK];
    for (int t = lane; t < NTOK; t += 32) dist[t] = g_dist[b][t];
    __syncwarp();

    int minR = FH, maxR = -1, minC = FH, maxC = -1;
    for (int k = 0; k < TOPK; k++) {
        float bv = -3e38f;
        int   bi = 0x7fffffff;
        for (int t = lane; t < NTOK; t += 32) {
            const float v = dist[t];
            if (v > bv || (v == bv && t < bi)) { bv = v; bi = t; }
        }
        #pragma unroll
        for (int o = 16; o; o >>= 1) {
            const float ov = __shfl_xor_sync(0xffffffffu, bv, o);
            const int   oi = __shfl_xor_sync(0xffffffffu, bi, o);
            if (ov > bv || (ov == bv && oi < bi)) { bv = ov; bi = oi; }
        }
        if (lane == 0) dist[bi] = -3e38f;
        __syncwarp();
        const int r = bi / FH, c = bi % FH;
        minR = min(minR, r); maxR = max(maxR, r);
        minC = min(minC, c); maxC = max(maxC, c);
    }
    if (lane == 0) {
        const int x_i = minR * PE, x_f = maxR * PE;
        const int y_i = minC * PE, y_f = maxC * PE;
        const int x0 = max(x_i, 0);
        const int y0 = max(y_i, 0);
        const int x1 = min(max(x_f, x_i + PE), IMG);
        const int y1 = min(max(y_f, y_i + PE), IMG);
        g_box[b][0] = x0; g_box[b][1] = x1;
        g_box[b][2] = y0; g_box[b][3] = y1;
    }
}

// ---------------------------------------------------------------------------
// Kernel B: bilinear crop-resize (align_corners), 16 output rows per CTA,
// input rows staged in shared memory with coalesced loads.
// grid = (28 row-tiles, 3 channels, 64 batches), block = 448 threads.
// ---------------------------------------------------------------------------
__global__ __launch_bounds__(IMG)
void crop_resize_kernel(const float* __restrict__ images, float* __restrict__ out) {
    __shared__ float srows[SROWS * IMG];   // 32.25 KB

    const int rt = blockIdx.x;           // row tile
    const int c  = blockIdx.y;
    const int b  = blockIdx.z;
    const int ox = threadIdx.x;

    const int x0 = g_box[b][0], x1 = g_box[b][1];
    const int y0 = g_box[b][2], y1 = g_box[b][3];

    const float scale = (float)(1.0 / 447.0);
    const float hm1 = __fadd_rn((float)(x1 - x0), -1.0f);
    const float wm1 = __fadd_rn((float)(y1 - y0), -1.0f);

    // Vertical input-row range covered by this tile (sy monotone in oy).
    const int oy0 = rt * ROWT;
    const float syA = __fadd_rn((float)x0, __fmul_rn(__fmul_rn((float)oy0, hm1), scale));
    const float syB = __fadd_rn((float)x0, __fmul_rn(__fmul_rn((float)(oy0 + ROWT - 1), hm1), scale));
    const int ystart = (int)floorf(syA);
    const int yloB   = (int)floorf(syB);
    const int yend   = max(yloB, min(yloB + 1, x1 - 1));
    const int nrows  = yend - ystart + 1;        // <= 18
    const int wspan  = y1 - y0;                  // needed columns [y0, y1)

    // Stage input rows: fully coalesced, high MLP (independent row loads).
    const float* __restrict__ img = images + (size_t)(b * NCH + c) * IMG * IMG;
    {
        const float* __restrict__ src = img + ystart * IMG + y0;
        if (ox < wspan) {
            #pragma unroll 4
            for (int r = 0; r < nrows; r++)
                srows[r * IMG + ox] = __ldg(src + r * IMG + ox);
        }
    }

    // Horizontal (per-thread, constant across rows).
    // Reference fp32 expression order, no FMA contraction.
    const float sx = __fadd_rn((float)y0, __fmul_rn(__fmul_rn((float)ox, wm1), scale));
    const int   xlo = (int)floorf(sx);
    const int   xhi = min(xlo + 1, y1 - 1);
    const float wx  = __fadd_rn(sx, -(float)xlo);
    const float wx1 = 1.f - wx;
    const int   clo = xlo - y0;
    const int   chi = xhi - y0;

    __syncthreads();

    float* __restrict__ op = out + ((size_t)(b * NCH + c) * IMG + oy0) * IMG + ox;

    #pragma unroll 4
    for (int r = 0; r < ROWT; r++) {
        const int oy = oy0 + r;
        const float sy  = __fadd_rn((float)x0, __fmul_rn(__fmul_rn((float)oy, hm1), scale));
        const int   ylo = (int)floorf(sy);
        const int   yhi = min(ylo + 1, x1 - 1);
        const float wy  = __fadd_rn(sy, -(float)ylo);
        const float wy1 = 1.f - wy;

        const float* __restrict__ s0 = srows + (ylo - ystart) * IMG;
        const float* __restrict__ s1 = srows + (yhi - ystart) * IMG;
        const float v00 = s0[clo];
        const float v01 = s0[chi];
        const float v10 = s1[clo];
        const float v11 = s1[chi];

        const float res = wy1 * wx1 * v00 + wy1 * wx * v01
                        + wy  * wx1 * v10 + wy  * wx * v11;
        op[(size_t)r * IMG] = res;
    }
}

// ---------------------------------------------------------------------------
extern "C" void kernel_launch(void* const* d_in, const int* in_sizes, int n_in,
                              void* d_out, int out_size) {
    const float* x      = (const float*)d_in[0];   // (64, 785, 768) fp32
    const float* images = (const float*)d_in[1];   // (64, 3, 448, 448) fp32
    float* out = (float*)d_out;                    // (64, 3, 448, 448) fp32

    dim3 gridA(TGRP, NB);
    sim_kernel<<<gridA, 128>>>(x);
    topk_box_kernel<<<NB, 32>>>();
    dim3 gridB(IMG / ROWT, NCH, NB);
    crop_resize_kernel<<<gridB, IMG>>>(images, out);
}